// round 12
// baseline (speedup 1.0000x reference)
#include <cuda_runtime.h>

// Problem dims (fixed by the dataset)
constexpr int L = 13;
constexpr int B = 16;
constexpr int S = 512;
constexpr int D = 768;
constexpr int W = 256;
constexpr int D4 = D / 4;          // 192 float4 per row

// Single fused kernel. One thread per output float4 (proven-best layout).
// Span lookup: block stages its sentence's 2KB seg row into smem (coalesced
// parallel load — nothing serial behind the barrier), then each warp runs a
// 32-ary search: 2 smem probe rounds + 3 ballots ~= 150 cycles total.
// Note: D4*W = 49152 is divisible by 256, so all threads of a block share b.
__global__ void __launch_bounds__(256) segment_sum_fused(
    const float4* __restrict__ hidden,   // [L,B,S,D4]
    const int*    __restrict__ seg,      // [B,S] sorted per row
    float4*       __restrict__ out       // [L,B,W,D4]
) {
    __shared__ int s_seg[S];             // 2KB

    int idx = blockIdx.x * blockDim.x + threadIdx.x;   // output float4 index
    int d4  = idx % D4;
    int row = idx / D4;            // l*B*W + b*W + w
    int w   = row % W;
    int bl  = row / W;             // l*B + b
    int b   = bl % B;              // block-uniform

    // Stage seg row (parallel coalesced: 2 loads/thread).
    #pragma unroll
    for (int i = threadIdx.x; i < S; i += 256) s_seg[i] = seg[b * S + i];
    __syncthreads();

    // Warp-cooperative 32-ary search in smem (same logic as R9, verified).
    const int lane = threadIdx.x & 31;
    int v1 = s_seg[lane * 16];
    unsigned m0 = __ballot_sync(0xFFFFFFFFu, v1 < w);    // lower_bound(w)
    unsigned m1 = __ballot_sync(0xFFFFFFFFu, v1 <= w);   // lower_bound(w+1)
    int c0 = __popc(m0), c1 = __popc(m1);
    int base0 = c0 ? (c0 - 1) * 16 + 1 : 0;
    int base1 = c1 ? (c1 - 1) * 16 + 1 : 0;

    int sub  = lane & 15;
    int base = (lane < 16) ? base0 : base1;
    int tgt  = (lane < 16) ? w : (w + 1);
    int pos  = base + sub;
    int v2   = (pos < S) ? s_seg[pos] : 0x7fffffff;
    unsigned m2 = __ballot_sync(0xFFFFFFFFu, v2 < tgt);
    int s0 = base0 + __popc(m2 & 0xFFFFu);
    int s1 = base1 + __popc(m2 >> 16);

    // Streaming body — byte-identical to the proven 78us kernel.
    const float4* src = hidden + ((long long)bl * S + s0) * D4 + d4;
    float4 acc = make_float4(0.f, 0.f, 0.f, 0.f);
    for (int s = s0; s < s1; ++s) {
        float4 v = *src;
        acc.x += v.x; acc.y += v.y; acc.z += v.z; acc.w += v.w;
        src += D4;
    }
    out[idx] = acc;
}

extern "C" void kernel_launch(void* const* d_in, const int* in_sizes, int n_in,
                              void* d_out, int out_size) {
    const float* hidden = (const float*)d_in[0];
    const int*   seg    = (const int*)d_in[1];
    // d_in[2] = num_words scalar — W hardcoded.

    long long total = (long long)L * B * W * D4;   // 10,223,616
    int threads = 256;
    int blocks = (int)(total / threads);           // 39936 exactly
    segment_sum_fused<<<blocks, threads>>>(
        (const float4*)hidden, seg, (float4*)d_out);
}